// round 4
// baseline (speedup 1.0000x reference)
#include <cuda_runtime.h>

// Problem constants (fixed by setup_inputs)
#define KK 64      // point clouds
#define DD 320     // feature dim
#define NN 2048    // points per cloud
#define MM 128     // clusters per cloud
#define SS (KK*MM) // 8192 total segments
#define CH 64      // feature-dim chunk per block in segment-sum kernel
#define NCH (DD/CH)
#define EPSV 1e-12f

// ---------------- scratch (device globals: no allocation allowed) -----------
__device__ int   g_counts[SS];
__device__ float g_lblsum[SS];
__device__ float g_coef[SS];   // cls_mask ? 1/max(norm,eps) : 0
__device__ float g_mask[SS];   // cls_mask as float
__device__ float g_v[DD];      // fn^T @ weight
__device__ int   g_maxsize;
__device__ int   g_nvalid;
__device__ float g_simsum;

// ---------------- kernel 0: zero scratch ------------------------------------
__global__ void k_zero() {
    int i = blockIdx.x * blockDim.x + threadIdx.x;
    if (i < SS) { g_counts[i] = 0; g_lblsum[i] = 0.f; }
    if (i < DD) g_v[i] = 0.f;
    if (i == 0) { g_maxsize = 0; g_nvalid = 0; g_simsum = 0.f; }
}

// ---------------- kernel 1: per-segment counts + label sums -----------------
__global__ void k_count(const int* __restrict__ clab,
                        const float* __restrict__ label) {
    int i = blockIdx.x * blockDim.x + threadIdx.x;
    if (i >= KK * NN) return;
    int k = i >> 11;                 // i / NN
    int s = k * MM + clab[i];
    atomicAdd(&g_counts[s], 1);
    atomicAdd(&g_lblsum[s], label[i]);
}

// ---------------- kernel 2: segment feature sums -> cluster means -----------
// grid (KK, NCH), block (32, 8). Shared accumulators padded to stride CH+1 so
// concurrent atomics from one warp (random clusters, same dd) spread banks:
// bank = (c*(CH+1)+dd) mod 32 = (c+dd) mod 32 with c random.
__global__ void k_featsum(const float* __restrict__ feat,
                          const int* __restrict__ clab,
                          float* __restrict__ means) {
    __shared__ float sums[MM * (CH + 1)];
    __shared__ int   cl[NN];
    const int k  = blockIdx.x;
    const int ch = blockIdx.y;
    const int tid = threadIdx.y * 32 + threadIdx.x;

    for (int i = tid; i < MM * (CH + 1); i += 256) sums[i] = 0.f;
    for (int i = tid; i < NN; i += 256) cl[i] = clab[k * NN + i];
    __syncthreads();

    const float* f = feat + ((size_t)k * DD + (size_t)ch * CH) * NN;

    for (int n0 = 0; n0 < NN; n0 += 32) {
        const int n = n0 + threadIdx.x;
        const int c = cl[n];
        float* dst = &sums[c * (CH + 1)];
        // batch the 8 coalesced loads, then 8 spread-bank shared atomics
        float v[CH / 8];
#pragma unroll
        for (int j = 0; j < CH / 8; j++) {
            int dd = j * 8 + threadIdx.y;
            v[j] = f[(size_t)dd * NN + n];
        }
#pragma unroll
        for (int j = 0; j < CH / 8; j++) {
            int dd = j * 8 + threadIdx.y;
            atomicAdd(&dst[dd], v[j]);
        }
    }
    __syncthreads();

    // write means = sum / max(count,1)
    for (int i = tid; i < MM * CH; i += 256) {
        int c  = i / CH;
        int dd = i - c * CH;
        float denom = fmaxf((float)g_counts[k * MM + c], 1.f);
        means[((size_t)(k * MM + c)) * DD + (size_t)ch * CH + dd] =
            sums[c * (CH + 1) + dd] / denom;
    }
}

// ---------------- kernel 3: per-segment norm, mask, maxsize, nvalid ---------
// one warp per segment
__global__ void k_seg(const float* __restrict__ means) {
    int w    = (blockIdx.x * blockDim.x + threadIdx.x) >> 5;
    int lane = threadIdx.x & 31;
    if (w >= SS) return;
    const float* row = means + (size_t)w * DD;
    float ss = 0.f;
    for (int i = lane; i < DD; i += 32) { float v = row[i]; ss += v * v; }
#pragma unroll
    for (int o = 16; o; o >>= 1) ss += __shfl_xor_sync(0xffffffffu, ss, o);
    if (lane == 0) {
        float norm = sqrtf(ss);
        int cnt    = g_counts[w];
        float lm   = g_lblsum[w] / fmaxf((float)cnt, 1.f);
        bool mask  = (lm > 0.5f) && (cnt > 0);
        g_coef[w]  = mask ? (1.f / fmaxf(norm, EPSV)) : 0.f;
        g_mask[w]  = mask ? 1.f : 0.f;
        if (mask) {
            atomicMax(&g_maxsize, cnt);
            atomicAdd(&g_nvalid, 1);
        }
    }
}

// ---------------- kernel 4: v = fn^T @ weight (320-vector) ------------------
// grid 32 blocks x 320 threads; each thread owns one feature dim
__global__ void k_v(const float* __restrict__ means) {
    const int t = threadIdx.x;           // 0..319
    const float maxs = fmaxf((float)g_maxsize, 1.f);
    float acc = 0.f;
    for (int s = blockIdx.x; s < SS; s += gridDim.x) {
        float a = g_coef[s] * (float)g_counts[s] / maxs; // mask folded into coef
        if (a != 0.f)                                     // uniform across block
            acc += means[(size_t)s * DD + t] * a;
    }
    atomicAdd(&g_v[t], acc);
}

// ---------------- kernel 5: sim_score[s] = fn[s] . v ------------------------
// one warp per segment
__global__ void k_sim(const float* __restrict__ means,
                      float* __restrict__ sim_out) {
    int w    = (blockIdx.x * blockDim.x + threadIdx.x) >> 5;
    int lane = threadIdx.x & 31;
    if (w >= SS) return;
    const float* row = means + (size_t)w * DD;
    float dot = 0.f;
    for (int i = lane; i < DD; i += 32) dot += row[i] * g_v[i];
#pragma unroll
    for (int o = 16; o; o >>= 1) dot += __shfl_xor_sync(0xffffffffu, dot, o);
    if (lane == 0) {
        float sim = dot * g_coef[w];
        sim_out[w] = sim;
        if (g_mask[w] != 0.f) atomicAdd(&g_simsum, sim);
    }
}

// ---------------- kernel 6: clean_mask --------------------------------------
__global__ void k_clean(const float* __restrict__ sim,
                        float* __restrict__ clean) {
    int s = blockIdx.x * blockDim.x + threadIdx.x;
    if (s >= SS) return;
    float mean_score = g_simsum / fmaxf((float)g_nvalid, 1.f);
    clean[s] = ((sim[s] > mean_score) && (g_mask[s] != 0.f)) ? 1.f : 0.f;
}

// ---------------- launch -----------------------------------------------------
extern "C" void kernel_launch(void* const* d_in, const int* in_sizes, int n_in,
                              void* d_out, int out_size) {
    const float* feat  = (const float*)d_in[0];   // (K, d, N)
    const float* label = (const float*)d_in[1];   // (K, N)
    const int*   clab  = (const int*)d_in[2];     // (K, N)

    float* out   = (float*)d_out;
    float* means = out;                        // (S, d)
    float* sim   = out + (size_t)SS * DD;      // (S,)
    float* clean = sim + SS;                   // (S,)

    k_zero<<<(SS + 255) / 256, 256>>>();
    k_count<<<(KK * NN + 255) / 256, 256>>>(clab, label);
    k_featsum<<<dim3(KK, NCH), dim3(32, 8)>>>(feat, clab, means);
    k_seg<<<SS / 8, 256>>>(means);
    k_v<<<32, DD>>>(means);
    k_sim<<<SS / 8, 256>>>(means, sim);
    k_clean<<<SS / 256, 256>>>(sim, clean);
}

// round 5
// speedup vs baseline: 1.4485x; 1.4485x over previous
#include <cuda_runtime.h>

// Problem constants (fixed by setup_inputs)
#define KK 64      // point clouds
#define DD 320     // feature dim
#define NN 2048    // points per cloud
#define MM 128     // clusters per cloud
#define SS (KK*MM) // 8192 total segments
#define CH 4       // feature dims per featsum block
#define NCH (DD/CH)
#define EPSV 1e-12f

// ---------------- scratch (device globals: no allocation allowed) -----------
__device__ int   g_counts[SS];
__device__ float g_lblsum[SS];
__device__ int   g_off[KK * (MM + 1)];
__device__ int   g_rank[KK * NN];     // sorted position of each point
__device__ float g_norm2[SS];
__device__ float g_coef[SS];          // cls_mask ? 1/max(norm,eps) : 0
__device__ float g_mask[SS];          // cls_mask as float
__device__ float g_v[DD];             // fn^T @ weight
__device__ int   g_maxsize;
__device__ int   g_nvalid;
__device__ float g_simsum;

// ---------------- kernel 0: zero the accumulators ---------------------------
__global__ void k_zero() {
    int i = blockIdx.x * blockDim.x + threadIdx.x;
    if (i < SS) g_norm2[i] = 0.f;
    if (i < DD) g_v[i] = 0.f;
    if (i == 0) { g_maxsize = 0; g_nvalid = 0; g_simsum = 0.f; }
}

// ---------------- kernel 1: per-cloud counting sort + label sums ------------
// one block per cloud
__global__ void k_sort(const int* __restrict__ clab,
                       const float* __restrict__ label) {
    __shared__ int   cl[NN];
    __shared__ int   hist[MM];
    __shared__ float lsum[MM];
    __shared__ int   off[MM + 1];
    __shared__ int   cur[MM];
    const int k = blockIdx.x;
    const int tid = threadIdx.x;

    for (int i = tid; i < MM; i += 256) { hist[i] = 0; lsum[i] = 0.f; cur[i] = 0; }
    __syncthreads();
    for (int n = tid; n < NN; n += 256) {
        int c = clab[k * NN + n];
        cl[n] = c;
        atomicAdd(&hist[c], 1);
        atomicAdd(&lsum[c], label[k * NN + n]);
    }
    __syncthreads();

    // exclusive scan over 128 bins: warp 0, 4 bins per lane
    if (tid < 32) {
        int l0 = hist[tid * 4 + 0], l1 = hist[tid * 4 + 1];
        int l2 = hist[tid * 4 + 2], l3 = hist[tid * 4 + 3];
        int tot = l0 + l1 + l2 + l3;
        int inc = tot;
#pragma unroll
        for (int d = 1; d < 32; d <<= 1) {
            int u = __shfl_up_sync(0xffffffffu, inc, d);
            if (tid >= d) inc += u;
        }
        int ex = inc - tot;
        off[tid * 4 + 0] = ex;            ex += l0;
        off[tid * 4 + 1] = ex;            ex += l1;
        off[tid * 4 + 2] = ex;            ex += l2;
        off[tid * 4 + 3] = ex;            ex += l3;
        if (tid == 31) off[MM] = ex;      // == NN
    }
    __syncthreads();

    for (int i = tid; i < MM; i += 256) {
        g_counts[k * MM + i] = hist[i];
        g_lblsum[k * MM + i] = lsum[i];
        g_off[k * (MM + 1) + i] = off[i];
    }
    if (tid == 0) g_off[k * (MM + 1) + MM] = off[MM];

    // scatter: assign sorted position to each point
    for (int n = tid; n < NN; n += 256) {
        int c = cl[n];
        int pos = off[c] + atomicAdd(&cur[c], 1);
        g_rank[k * NN + n] = pos;
    }
}

// ---------------- kernel 2: atomic-free segment feature sums ----------------
// grid (KK, NCH), block 128 = 4 warps; warp w owns feature dim ch*CH + w.
// Stage the 2048-float row into shared IN SORTED ORDER (coalesced global read,
// permuted STS), then each lane serially sums its 4 contiguous cluster
// segments with plain LDS. Zero atomics on the hot path.
__global__ void k_featsum(const float* __restrict__ feat,
                          float* __restrict__ means) {
    __shared__ float rows[CH][NN];     // 32 KB
    __shared__ int   rnk[NN];          // 8 KB
    __shared__ int   off[MM + 1];
    __shared__ float bins[MM][CH + 1]; // pad to spread banks on writes
    const int k   = blockIdx.x;
    const int ch  = blockIdx.y;
    const int tid = threadIdx.x;
    const int w   = tid >> 5;
    const int lane = tid & 31;

    for (int i = tid; i < NN; i += 128) rnk[i] = g_rank[k * NN + i];
    for (int i = tid; i <= MM; i += 128) off[i] = g_off[k * (MM + 1) + i];
    __syncthreads();

    const int dd = ch * CH + w;
    const float* f = feat + ((size_t)k * DD + dd) * NN;
    float* rowp = rows[w];

    // stage permuted
#pragma unroll 4
    for (int j0 = 0; j0 < NN; j0 += 32) {
        int n = j0 + lane;
        rowp[rnk[n]] = __ldg(&f[n]);
    }
    __syncwarp();

    // reduce: lane handles 4 contiguous clusters
    const int c0 = lane * 4;
#pragma unroll
    for (int cc = 0; cc < 4; cc++) {
        int c = c0 + cc;
        int a = off[c], b = off[c + 1];
        float s = 0.f;
        for (int j = a; j < b; j++) s += rowp[j];
        bins[c][w] = s;
    }
    __syncthreads();

    // write means + norm^2 partials
    for (int i = tid; i < MM * CH; i += 128) {
        int c   = i >> 2;       // i / CH
        int dd2 = i & 3;        // i % CH
        float denom = fmaxf((float)g_counts[k * MM + c], 1.f);
        float m = bins[c][dd2] / denom;
        means[(size_t)(k * MM + c) * DD + ch * CH + dd2] = m;
        atomicAdd(&g_norm2[k * MM + c], m * m);
    }
}

// ---------------- kernel 3: scalar per-segment coef/mask/maxsize/nvalid -----
__global__ void k_seg2() {
    int s = blockIdx.x * blockDim.x + threadIdx.x;
    if (s >= SS) return;
    int cnt   = g_counts[s];
    float lm  = g_lblsum[s] / fmaxf((float)cnt, 1.f);
    bool mask = (lm > 0.5f) && (cnt > 0);
    float norm = sqrtf(g_norm2[s]);
    g_coef[s] = mask ? (1.f / fmaxf(norm, EPSV)) : 0.f;
    g_mask[s] = mask ? 1.f : 0.f;
    // warp pre-reduce before the single-address atomics
    int vflag = mask ? 1 : 0;
    int vmax  = mask ? cnt : 0;
    int wsum  = __reduce_add_sync(0xffffffffu, vflag);
    int wmax  = __reduce_max_sync(0xffffffffu, vmax);
    if ((threadIdx.x & 31) == 0) {
        if (wsum) atomicAdd(&g_nvalid, wsum);
        if (wmax) atomicMax(&g_maxsize, wmax);
    }
}

// ---------------- kernel 4: v = fn^T @ weight (320-vector) ------------------
// thread t owns feature dim t; 128 blocks stride over segments
__global__ void k_v(const float* __restrict__ means) {
    const int t = threadIdx.x;           // 0..319
    const float maxs = fmaxf((float)g_maxsize, 1.f);
    float acc = 0.f;
    for (int s = blockIdx.x; s < SS; s += gridDim.x) {
        float a = g_coef[s] * (float)g_counts[s] / maxs; // mask folded into coef
        if (a != 0.f)                                     // uniform across block
            acc += means[(size_t)s * DD + t] * a;
    }
    atomicAdd(&g_v[t], acc);
}

// ---------------- kernel 5: sim_score[s] = coef[s] * (means[s] . v) ---------
// one warp per segment, float4 loads, v cached in shared
__global__ void k_sim(const float* __restrict__ means,
                      float* __restrict__ sim_out) {
    __shared__ float vv[DD];
    for (int i = threadIdx.x; i < DD; i += 256) vv[i] = g_v[i];
    __syncthreads();
    int w    = (blockIdx.x * blockDim.x + threadIdx.x) >> 5;
    int lane = threadIdx.x & 31;
    if (w >= SS) return;
    const float4* r4 = (const float4*)(means + (size_t)w * DD);
    const float4* v4 = (const float4*)vv;
    float dot = 0.f;
#pragma unroll
    for (int i = lane; i < DD / 4; i += 32) {
        float4 a = r4[i];
        float4 b = v4[i];
        dot += a.x * b.x + a.y * b.y + a.z * b.z + a.w * b.w;
    }
#pragma unroll
    for (int o = 16; o; o >>= 1) dot += __shfl_xor_sync(0xffffffffu, dot, o);
    if (lane == 0) {
        float sim = dot * g_coef[w];
        sim_out[w] = sim;
        if (g_mask[w] != 0.f) atomicAdd(&g_simsum, sim);
    }
}

// ---------------- kernel 6: clean_mask --------------------------------------
__global__ void k_clean(const float* __restrict__ sim,
                        float* __restrict__ clean) {
    int s = blockIdx.x * blockDim.x + threadIdx.x;
    if (s >= SS) return;
    float mean_score = g_simsum / fmaxf((float)g_nvalid, 1.f);
    clean[s] = ((sim[s] > mean_score) && (g_mask[s] != 0.f)) ? 1.f : 0.f;
}

// ---------------- launch -----------------------------------------------------
extern "C" void kernel_launch(void* const* d_in, const int* in_sizes, int n_in,
                              void* d_out, int out_size) {
    const float* feat  = (const float*)d_in[0];   // (K, d, N)
    const float* label = (const float*)d_in[1];   // (K, N)
    const int*   clab  = (const int*)d_in[2];     // (K, N)

    float* out   = (float*)d_out;
    float* means = out;                        // (S, d)
    float* sim   = out + (size_t)SS * DD;      // (S,)
    float* clean = sim + SS;                   // (S,)

    k_zero<<<(SS + 255) / 256, 256>>>();
    k_sort<<<KK, 256>>>(clab, label);
    k_featsum<<<dim3(KK, NCH), 128>>>(feat, means);
    k_seg2<<<SS / 256, 256>>>();
    k_v<<<128, DD>>>(means);
    k_sim<<<SS / 8, 256>>>(means, sim);
    k_clean<<<SS / 256, 256>>>(sim, clean);
}